// round 8
// baseline (speedup 1.0000x reference)
#include <cuda_runtime.h>
#include <cuda_bf16.h>
#include <cstdint>

// YOLO loss: persistent double-buffered cp.async pipeline + smem transpose.
// pred/target: (16384, 7, 7, 30) fp32. Output: scalar fp32.

#define S 7
#define CH 30
#define TOTAL_CELLS (16384 * S * S)          // 802816
#define STEP (1.0f / 7.0f)
#define LAMBDA_COORD 5.0f
#define LAMBDA_NOOBJ 0.5f
#define EPS 1e-10f
#define INV_N (1.0f / 16384.0f)

#define TPB 128
#define CELLS_PER_TILE 128
#define TILE_FLOATS (CELLS_PER_TILE * CH)     // 3840 floats per array
#define STAGE_FLOATS (TILE_FLOATS * 2)        // pred + target = 7680 floats
#define STAGE_BYTES (STAGE_FLOATS * 4)        // 30720 B
#define SMEM_BYTES (2 * STAGE_BYTES)          // 61440 B (double buffer)
#define NTILES (TOTAL_CELLS / CELLS_PER_TILE) // 6272
#define GRID 456                              // 152 SMs * 3 blocks

__device__ __forceinline__ uint32_t smem_u32(const void* p) {
    uint32_t a;
    asm("{ .reg .u64 t; cvta.to.shared.u64 t, %1; cvt.u32.u64 %0, t; }" : "=r"(a) : "l"(p));
    return a;
}
__device__ __forceinline__ void cp16(uint32_t dst, const void* src) {
    asm volatile("cp.async.cg.shared.global [%0], [%1], 16;" :: "r"(dst), "l"(src));
}
__device__ __forceinline__ void cp_commit() {
    asm volatile("cp.async.commit_group;" ::: "memory");
}
template <int N>
__device__ __forceinline__ void cp_wait() {
    asm volatile("cp.async.wait_group %0;" :: "n"(N) : "memory");
}

__device__ __forceinline__ float warp_reduce(float v) {
#pragma unroll
    for (int off = 16; off > 0; off >>= 1)
        v += __shfl_xor_sync(0xFFFFFFFFu, v, off);
    return v;
}

__global__ __launch_bounds__(TPB)
void yolo_loss_kernel(const float* __restrict__ pred,
                      const float* __restrict__ target,
                      float* __restrict__ out) {
    extern __shared__ float smem[];  // [2][STAGE_FLOATS]
    const uint32_t sbase = smem_u32(smem);
    const int tid = threadIdx.x;

    // ---- producer helper: issue cp.asyncs for one tile into a stage ----
    auto prefetch = [&](int tile, int stage) {
        const uint32_t pdst = sbase + stage * STAGE_BYTES;
        const uint32_t tdst = pdst + TILE_FLOATS * 4;
        const float4* pg = reinterpret_cast<const float4*>(pred + (size_t)tile * TILE_FLOATS);
        const float4* tg = reinterpret_cast<const float4*>(target + (size_t)tile * TILE_FLOATS);
#pragma unroll
        for (int j = 0; j < 7; j++) {
            cp16(pdst + (tid + TPB * j) * 16, pg + tid + TPB * j);
            cp16(tdst + (tid + TPB * j) * 16, tg + tid + TPB * j);
        }
        if (tid < (TILE_FLOATS / 4 - 7 * TPB)) {  // 64-thread tail
            cp16(pdst + (tid + TPB * 7) * 16, pg + tid + TPB * 7);
            cp16(tdst + (tid + TPB * 7) * 16, tg + tid + TPB * 7);
        }
    };

    float acc = 0.0f;
    const int t0 = blockIdx.x;

    if (t0 < NTILES) {
        prefetch(t0, 0);
        cp_commit();

        int k = 0;
        for (int tile = t0; tile < NTILES; tile += GRID, k++) {
            const int next = tile + GRID;
            if (next < NTILES) {
                prefetch(next, (k + 1) & 1);
                cp_commit();
                cp_wait<1>();
            } else {
                cp_wait<0>();
            }
            __syncthreads();

            // ---- compute on stage k&1 ----
            const float* sp = smem + (k & 1) * STAGE_FLOATS;
            const float* st = sp + TILE_FLOATS;

            float pv[CH], tv[CH];
            {
                const float2* sp2 = reinterpret_cast<const float2*>(sp) + tid * (CH / 2);
                const float2* st2 = reinterpret_cast<const float2*>(st) + tid * (CH / 2);
#pragma unroll
                for (int i = 0; i < CH / 2; i++) {
                    float2 a = sp2[i];
                    pv[2 * i] = a.x; pv[2 * i + 1] = a.y;
                }
#pragma unroll
                for (int i = 0; i < CH / 2; i++) {
                    float2 a = st2[i];
                    tv[2 * i] = a.x; tv[2 * i + 1] = a.y;
                }
            }

            const int cell = tile * CELLS_PER_TILE + tid;
            const int rem = cell % (S * S);
            const float gy = (float)(rem / S);   // axis 1
            const float gx = (float)(rem % S);   // axis 2

            const float cell_mask = (tv[9] > 0.0f) ? 1.0f : 0.0f;

            float iou[2];
#pragma unroll
            for (int b = 0; b < 2; b++) {
                const int o = 5 * b;
                float pw = fmaxf(pv[o + 2], 0.0f);
                float ph = fmaxf(pv[o + 3], 0.0f);
                float px = fmaxf((pv[o + 0] + gx) * STEP - pv[o + 2] * 0.5f, 0.0f);
                float py = fmaxf((pv[o + 1] + gy) * STEP - pv[o + 3] * 0.5f, 0.0f);
                float tw = fmaxf(tv[o + 2], 0.0f);
                float th = fmaxf(tv[o + 3], 0.0f);
                float tx = fmaxf((tv[o + 0] + gx) * STEP - tv[o + 2] * 0.5f, 0.0f);
                float ty = fmaxf((tv[o + 1] + gy) * STEP - tv[o + 3] * 0.5f, 0.0f);

                float inter_w = fmaxf(pw + tw - (fmaxf(px + pw, tx + tw) - fminf(px, tx)), 0.0f);
                float inter_h = fmaxf(ph + th - (fmaxf(py + ph, ty + th) - fminf(py, ty)), 0.0f);
                float inter = inter_w * inter_h;
                float uni = pw * ph + tw * th - inter;
                iou[b] = inter / (uni + EPS);
            }

            const int resp = (iou[1] > iou[0]) ? 1 : 0;  // ties -> box 0

            float loss = 0.0f;
#pragma unroll
            for (int b = 0; b < 2; b++) {
                const int o = 5 * b;
                const float ob = (b == resp) ? cell_mask : 0.0f;
                float c = 0.0f;
#pragma unroll
                for (int q = 0; q < 4; q++) {
                    float d = pv[o + q] - tv[o + q];
                    c += d * d;
                }
                loss += LAMBDA_COORD * ob * c;
                float dc = pv[o + 4] - iou[b];
                loss += ob * dc * dc;
                loss += LAMBDA_NOOBJ * (1.0f - ob) * pv[o + 4] * pv[o + 4];
            }

            float cl = 0.0f;
#pragma unroll
            for (int c = 10; c < CH; c++) {
                float d = pv[c] - tv[c];
                cl += d * d;
            }
            loss += cell_mask * cl;

            acc += loss;

            __syncthreads();  // stage reusable by next prefetch
        }
    }

    // ---- block reduction (4 warps), one atomic per block ----
    __shared__ float warp_sums[TPB / 32];
    acc = warp_reduce(acc);
    const int lane = tid & 31;
    const int wid = tid >> 5;
    if (lane == 0) warp_sums[wid] = acc;
    __syncthreads();
    if (wid == 0) {
        float v = (lane < (TPB / 32)) ? warp_sums[lane] : 0.0f;
        v = warp_reduce(v);
        if (lane == 0) atomicAdd(out, v * INV_N);
    }
}

extern "C" void kernel_launch(void* const* d_in, const int* in_sizes, int n_in,
                              void* d_out, int out_size) {
    const float* pred = (const float*)d_in[0];
    const float* target = (const float*)d_in[1];
    float* out = (float*)d_out;

    static bool attr_set = false;
    if (!attr_set) {
        cudaFuncSetAttribute(yolo_loss_kernel,
                             cudaFuncAttributeMaxDynamicSharedMemorySize, SMEM_BYTES);
        attr_set = true;
    }

    cudaMemsetAsync(out, 0, (size_t)out_size * sizeof(float));
    yolo_loss_kernel<<<GRID, TPB, SMEM_BYTES>>>(pred, target, out);
}

// round 10
// speedup vs baseline: 1.1778x; 1.1778x over previous
#include <cuda_runtime.h>
#include <cuda_bf16.h>
#include <cstdint>

// YOLO loss: single-stage smem tile, cp.async staging, 2 threads/cell role split.
// pred/target: (16384, 7, 7, 30) fp32. Output: scalar fp32.

#define S 7
#define CH 30
#define TOTAL_CELLS (16384 * S * S)          // 802816
#define STEP (1.0f / 7.0f)
#define LAMBDA_COORD 5.0f
#define LAMBDA_NOOBJ 0.5f
#define EPS 1e-10f
#define INV_N (1.0f / 16384.0f)

#define TPB 256
#define CELLS_PER_TILE 128
#define TILE_FLOATS (CELLS_PER_TILE * CH)     // 3840 floats per array
#define VEC4 (TILE_FLOATS / 4)                // 960 float4 per array
#define NBLOCKS (TOTAL_CELLS / CELLS_PER_TILE) // 6272

__device__ __forceinline__ uint32_t smem_u32(const void* p) {
    uint32_t a;
    asm("{ .reg .u64 t; cvta.to.shared.u64 t, %1; cvt.u32.u64 %0, t; }" : "=r"(a) : "l"(p));
    return a;
}
__device__ __forceinline__ void cp16(uint32_t dst, const void* src) {
    asm volatile("cp.async.cg.shared.global [%0], [%1], 16;" :: "r"(dst), "l"(src));
}
__device__ __forceinline__ void cp_commit() {
    asm volatile("cp.async.commit_group;" ::: "memory");
}
__device__ __forceinline__ void cp_wait0() {
    asm volatile("cp.async.wait_group 0;" ::: "memory");
}

__device__ __forceinline__ float warp_reduce(float v) {
#pragma unroll
    for (int off = 16; off > 0; off >>= 1)
        v += __shfl_xor_sync(0xFFFFFFFFu, v, off);
    return v;
}

__global__ __launch_bounds__(TPB, 6)
void yolo_loss_kernel(const float* __restrict__ pred,
                      const float* __restrict__ target,
                      float* __restrict__ out) {
    __shared__ float sm[2 * TILE_FLOATS];     // [pred tile | target tile], 30720 B
    const uint32_t sbase = smem_u32(sm);
    const int tid = threadIdx.x;

    // ---- coalesced cp.async staging: 960 float4 per array ----
    {
        const float4* pg = reinterpret_cast<const float4*>(pred + (size_t)blockIdx.x * TILE_FLOATS);
        const float4* tg = reinterpret_cast<const float4*>(target + (size_t)blockIdx.x * TILE_FLOATS);
        const uint32_t tdst = sbase + TILE_FLOATS * 4;
#pragma unroll
        for (int j = 0; j < 3; j++) {
            cp16(sbase + (tid + TPB * j) * 16, pg + tid + TPB * j);
            cp16(tdst + (tid + TPB * j) * 16, tg + tid + TPB * j);
        }
        if (tid < (VEC4 - 3 * TPB)) {  // 192-thread tail
            cp16(sbase + (tid + TPB * 3) * 16, pg + tid + TPB * 3);
            cp16(tdst + (tid + TPB * 3) * 16, tg + tid + TPB * 3);
        }
        cp_commit();
    }
    cp_wait0();
    __syncthreads();

    const int c = tid & (CELLS_PER_TILE - 1);   // local cell
    float loss = 0.0f;

    if (tid < CELLS_PER_TILE) {
        // ---- role A: channels 0..13 (boxes, IoU, conf, coord, noobj, class 10-13) ----
        float pv[14], tv[14];
        {
            const float2* sp2 = reinterpret_cast<const float2*>(sm) + c * 15;
            const float2* st2 = reinterpret_cast<const float2*>(sm + TILE_FLOATS) + c * 15;
#pragma unroll
            for (int i = 0; i < 7; i++) {
                float2 a = sp2[i];
                pv[2 * i] = a.x; pv[2 * i + 1] = a.y;
            }
#pragma unroll
            for (int i = 0; i < 7; i++) {
                float2 a = st2[i];
                tv[2 * i] = a.x; tv[2 * i + 1] = a.y;
            }
        }

        const int cell = blockIdx.x * CELLS_PER_TILE + c;
        const int rem = cell % (S * S);
        const float gy = (float)(rem / S);   // axis 1
        const float gx = (float)(rem % S);   // axis 2

        const float cell_mask = (tv[9] > 0.0f) ? 1.0f : 0.0f;

        float iou[2];
#pragma unroll
        for (int b = 0; b < 2; b++) {
            const int o = 5 * b;
            float pw = fmaxf(pv[o + 2], 0.0f);
            float ph = fmaxf(pv[o + 3], 0.0f);
            float px = fmaxf((pv[o + 0] + gx) * STEP - pv[o + 2] * 0.5f, 0.0f);
            float py = fmaxf((pv[o + 1] + gy) * STEP - pv[o + 3] * 0.5f, 0.0f);
            float tw = fmaxf(tv[o + 2], 0.0f);
            float th = fmaxf(tv[o + 3], 0.0f);
            float tx = fmaxf((tv[o + 0] + gx) * STEP - tv[o + 2] * 0.5f, 0.0f);
            float ty = fmaxf((tv[o + 1] + gy) * STEP - tv[o + 3] * 0.5f, 0.0f);

            float inter_w = fmaxf(pw + tw - (fmaxf(px + pw, tx + tw) - fminf(px, tx)), 0.0f);
            float inter_h = fmaxf(ph + th - (fmaxf(py + ph, ty + th) - fminf(py, ty)), 0.0f);
            float inter = inter_w * inter_h;
            float uni = pw * ph + tw * th - inter;
            iou[b] = inter / (uni + EPS);
        }

        const int resp = (iou[1] > iou[0]) ? 1 : 0;  // ties -> box 0

#pragma unroll
        for (int b = 0; b < 2; b++) {
            const int o = 5 * b;
            const float ob = (b == resp) ? cell_mask : 0.0f;
            float cc = 0.0f;
#pragma unroll
            for (int q = 0; q < 4; q++) {
                float d = pv[o + q] - tv[o + q];
                cc += d * d;
            }
            loss += LAMBDA_COORD * ob * cc;
            float dc = pv[o + 4] - iou[b];
            loss += ob * dc * dc;
            loss += LAMBDA_NOOBJ * (1.0f - ob) * pv[o + 4] * pv[o + 4];
        }

        // class channels 10..13
        float cl = 0.0f;
#pragma unroll
        for (int q = 10; q < 14; q++) {
            float d = pv[q] - tv[q];
            cl += d * d;
        }
        loss += cell_mask * cl;
    } else {
        // ---- role B: class channels 14..29 ----
        const float mt = sm[TILE_FLOATS + c * CH + 9];
        const float cell_mask = (mt > 0.0f) ? 1.0f : 0.0f;

        const float2* sp2 = reinterpret_cast<const float2*>(sm) + c * 15 + 7;
        const float2* st2 = reinterpret_cast<const float2*>(sm + TILE_FLOATS) + c * 15 + 7;
        float cl = 0.0f;
#pragma unroll
        for (int i = 0; i < 8; i++) {
            float2 a = sp2[i];
            float2 b = st2[i];
            float d0 = a.x - b.x;
            float d1 = a.y - b.y;
            cl += d0 * d0 + d1 * d1;
        }
        loss = cell_mask * cl;
    }

    // ---- block reduction (8 warps), one atomic per block ----
    __shared__ float warp_sums[TPB / 32];
    loss = warp_reduce(loss);
    const int lane = tid & 31;
    const int wid = tid >> 5;
    if (lane == 0) warp_sums[wid] = loss;
    __syncthreads();
    if (wid == 0) {
        float v = (lane < (TPB / 32)) ? warp_sums[lane] : 0.0f;
        v = warp_reduce(v);
        if (lane == 0) atomicAdd(out, v * INV_N);
    }
}

extern "C" void kernel_launch(void* const* d_in, const int* in_sizes, int n_in,
                              void* d_out, int out_size) {
    const float* pred = (const float*)d_in[0];
    const float* target = (const float*)d_in[1];
    float* out = (float*)d_out;

    static bool attr_set = false;
    if (!attr_set) {
        // allow max smem carveout so 7 blocks (215 KB aggregate) can co-reside
        cudaFuncSetAttribute(yolo_loss_kernel,
                             cudaFuncAttributePreferredSharedMemoryCarveout, 100);
        attr_set = true;
    }

    cudaMemsetAsync(out, 0, (size_t)out_size * sizeof(float));
    yolo_loss_kernel<<<NBLOCKS, TPB>>>(pred, target, out);
}